// round 13
// baseline (speedup 1.0000x reference)
#include <cuda_runtime.h>

// AdaPool2D, R11 (resubmit after infra failure): R8 structure (2 outputs/thread,
// 8 independent 16B loads, paired reciprocals = 11 MUFU/channel) + safe trims:
//  - int32 index math (all element offsets < 2^31; kills IMAD.WIDE chains)
//  - __ldcs/__stcs streaming cache hints (zero-reuse workload, evict-first)
//  - __expf kept (maps to FMUL+MUFU.EX2; __exp2f does not exist device-side)
// R8 ran at exactly its achieved-BW limit (6.0 TB/s); goal: creep toward 6.3.

#define BDIM 32
#define WDIM 224
#define HDIM 224
#define WO 112
#define HO 112
#define C4 16  // 64 channels / 4 floats per thread

__device__ __forceinline__ float adapool1(float a, float b, float c, float d,
                                          float mk, float omk) {
    // --- exponential-maximum (softmax) pooling, no shift (inputs ~N(0,1)) ---
    float ea = __expf(a), eb = __expf(b), ec = __expf(c), ed = __expf(d);
    float den = (ea + eb) + (ec + ed);
    float num = fmaf(a, ea, fmaf(b, eb, fmaf(c, ec, d * ed)));

    // --- eDSCW: dsc = 2*avg*x / (avg^2 + x^2), softmax over window ---
    float s   = (a + b) + (c + d);
    float av2 = (s * s) * 0.0625f;   // avg^2
    float ta  = s * 0.5f;            // 2*avg
    float na = fmaf(a, a, av2);
    float nb = fmaf(b, b, av2);
    float nc = fmaf(c, c, av2);
    float nd = fmaf(d, d, av2);
    // paired reciprocals: one MUFU.RCP serves two positive denominators
    float rab = __fdividef(1.0f, na * nb);
    float rcd = __fdividef(1.0f, nc * nd);
    float fa = __expf((ta * a) * (rab * nb));
    float fb = __expf((ta * b) * (rab * na));
    float fc = __expf((ta * c) * (rcd * nd));
    float fd = __expf((ta * d) * (rcd * nc));
    float den2 = (fa + fb) + (fc + fd);
    float num2 = fmaf(a, fa, fmaf(b, fb, fmaf(c, fc, d * fd)));

    // paired softmax denominators folded into the blend:
    // result = rr * (mk*num*den2 + omk*num2*den),  rr = 1/(den*den2)
    float rr = __fdividef(1.0f, den * den2);
    float t2 = (omk * num2) * den;
    return rr * fmaf(mk * num, den2, t2);
}

__device__ __forceinline__ float4 ada4(float4 p00, float4 p01, float4 p10, float4 p11,
                                       float mk, float omk) {
    float4 o;
    o.x = adapool1(p00.x, p01.x, p10.x, p11.x, mk, omk);
    o.y = adapool1(p00.y, p01.y, p10.y, p11.y, mk, omk);
    o.z = adapool1(p00.z, p01.z, p10.z, p11.z, mk, omk);
    o.w = adapool1(p00.w, p01.w, p10.w, p11.w, mk, omk);
    return o;
}

__global__ void __launch_bounds__(256)
adapool2d_kernel(const float4* __restrict__ in,
                 const float* __restrict__ mask,
                 float4* __restrict__ out) {
    // x covers (ho, c4): 112*16 = 1792 threads = 7 blocks of 256 exactly.
    // y = wo-pair (56): each thread computes wo = 2*wp and 2*wp+1. z = b.
    int i  = blockIdx.x * blockDim.x + threadIdx.x;
    int c4 = i & (C4 - 1);
    int ho = i >> 4;
    int wp = blockIdx.y;
    int b  = blockIdx.z;

    float mk  = __ldg(mask);
    float omk = 1.0f - mk;

    // int32 element offsets (input is 25.7M float4 < 2^31)
    int ibase = ((b * WDIM + 4 * wp) * HDIM + 2 * ho) * C4 + c4;
    const float4* base = in + ibase;
    const int rs = HDIM * C4;  // input w-row stride in float4 (3584)

    // 8 independent 16B streaming loads (two 2x2 windows): MLP=8
    float4 p00 = __ldcs(base);
    float4 p01 = __ldcs(base + C4);
    float4 p10 = __ldcs(base + rs);
    float4 p11 = __ldcs(base + rs + C4);
    float4 q00 = __ldcs(base + 2 * rs);
    float4 q01 = __ldcs(base + 2 * rs + C4);
    float4 q10 = __ldcs(base + 3 * rs);
    float4 q11 = __ldcs(base + 3 * rs + C4);

    float4 op = ada4(p00, p01, p10, p11, mk, omk);
    float4 oq = ada4(q00, q01, q10, q11, mk, omk);

    int obase = ((b * WO + 2 * wp) * HO + ho) * C4 + c4;
    __stcs(out + obase, op);
    __stcs(out + obase + HO * C4, oq);
}

extern "C" void kernel_launch(void* const* d_in, const int* in_sizes, int n_in,
                              void* d_out, int out_size) {
    const float4* in   = (const float4*)d_in[0];
    const float*  mask = (const float*)d_in[1];
    float4*       out  = (float4*)d_out;

    dim3 block(256);
    dim3 grid(HO * C4 / 256, WO / 2, BDIM);  // (7, 56, 32)
    adapool2d_kernel<<<grid, block>>>(in, mask, out);
}

// round 15
// speedup vs baseline: 1.0170x; 1.0170x over previous
#include <cuda_runtime.h>

// AdaPool2D, R13: R11 math (2 outputs/thread, 8 chains, paired reciprocals,
// 11 MUFU/channel) with block 128 instead of 256.
// R11 profile: occ 64.5% (40 regs -> 5x256-thread blocks = 40/64 warps),
// issue 85.8%, no pipe saturated -> latency-limited residual.
// 128-thread blocks: 12 blocks/SM = 48 warps (75%) at the same 40 regs.

#define BDIM 32
#define WDIM 224
#define HDIM 224
#define WO 112
#define HO 112
#define C4 16  // 64 channels / 4 floats per thread

__device__ __forceinline__ float adapool1(float a, float b, float c, float d,
                                          float mk, float omk) {
    // --- exponential-maximum (softmax) pooling, no shift (inputs ~N(0,1)) ---
    float ea = __expf(a), eb = __expf(b), ec = __expf(c), ed = __expf(d);
    float den = (ea + eb) + (ec + ed);
    float num = fmaf(a, ea, fmaf(b, eb, fmaf(c, ec, d * ed)));

    // --- eDSCW: dsc = 2*avg*x / (avg^2 + x^2), softmax over window ---
    float s   = (a + b) + (c + d);
    float av2 = (s * s) * 0.0625f;   // avg^2
    float ta  = s * 0.5f;            // 2*avg
    float na = fmaf(a, a, av2);
    float nb = fmaf(b, b, av2);
    float nc = fmaf(c, c, av2);
    float nd = fmaf(d, d, av2);
    // paired reciprocals: one MUFU.RCP serves two positive denominators
    float rab = __fdividef(1.0f, na * nb);
    float rcd = __fdividef(1.0f, nc * nd);
    float fa = __expf((ta * a) * (rab * nb));
    float fb = __expf((ta * b) * (rab * na));
    float fc = __expf((ta * c) * (rcd * nd));
    float fd = __expf((ta * d) * (rcd * nc));
    float den2 = (fa + fb) + (fc + fd);
    float num2 = fmaf(a, fa, fmaf(b, fb, fmaf(c, fc, d * fd)));

    // paired softmax denominators folded into the blend:
    // result = rr * (mk*num*den2 + omk*num2*den),  rr = 1/(den*den2)
    float rr = __fdividef(1.0f, den * den2);
    float t2 = (omk * num2) * den;
    return rr * fmaf(mk * num, den2, t2);
}

__device__ __forceinline__ float4 ada4(float4 p00, float4 p01, float4 p10, float4 p11,
                                       float mk, float omk) {
    float4 o;
    o.x = adapool1(p00.x, p01.x, p10.x, p11.x, mk, omk);
    o.y = adapool1(p00.y, p01.y, p10.y, p11.y, mk, omk);
    o.z = adapool1(p00.z, p01.z, p10.z, p11.z, mk, omk);
    o.w = adapool1(p00.w, p01.w, p10.w, p11.w, mk, omk);
    return o;
}

__global__ void __launch_bounds__(128)
adapool2d_kernel(const float4* __restrict__ in,
                 const float* __restrict__ mask,
                 float4* __restrict__ out) {
    // x covers (ho, c4): 112*16 = 1792 threads = 14 blocks of 128 exactly.
    // y = wo-pair (56): each thread computes wo = 2*wp and 2*wp+1. z = b.
    int i  = blockIdx.x * blockDim.x + threadIdx.x;
    int c4 = i & (C4 - 1);
    int ho = i >> 4;
    int wp = blockIdx.y;
    int b  = blockIdx.z;

    float mk  = __ldg(mask);
    float omk = 1.0f - mk;

    // int32 element offsets (input is 25.7M float4 < 2^31)
    int ibase = ((b * WDIM + 4 * wp) * HDIM + 2 * ho) * C4 + c4;
    const float4* base = in + ibase;
    const int rs = HDIM * C4;  // input w-row stride in float4 (3584)

    // 8 independent 16B streaming loads (two 2x2 windows): MLP=8
    float4 p00 = __ldcs(base);
    float4 p01 = __ldcs(base + C4);
    float4 p10 = __ldcs(base + rs);
    float4 p11 = __ldcs(base + rs + C4);
    float4 q00 = __ldcs(base + 2 * rs);
    float4 q01 = __ldcs(base + 2 * rs + C4);
    float4 q10 = __ldcs(base + 3 * rs);
    float4 q11 = __ldcs(base + 3 * rs + C4);

    float4 op = ada4(p00, p01, p10, p11, mk, omk);
    float4 oq = ada4(q00, q01, q10, q11, mk, omk);

    int obase = ((b * WO + 2 * wp) * HO + ho) * C4 + c4;
    __stcs(out + obase, op);
    __stcs(out + obase + HO * C4, oq);
}

extern "C" void kernel_launch(void* const* d_in, const int* in_sizes, int n_in,
                              void* d_out, int out_size) {
    const float4* in   = (const float4*)d_in[0];
    const float*  mask = (const float*)d_in[1];
    float4*       out  = (float4*)d_out;

    dim3 block(128);
    dim3 grid(HO * C4 / 128, WO / 2, BDIM);  // (14, 56, 32)
    adapool2d_kernel<<<grid, block>>>(in, mask, out);
}